// round 10
// baseline (speedup 1.0000x reference)
#include <cuda_runtime.h>
#include <cuda_fp16.h>
#include <math.h>
#include <stdint.h>

#define NHALF 8192
#define NTOT  16384
#define DIMK  128
#define NAB2  2048                 // 64 x 32 ab tiles (128x256)
#define NTRI2 1056                 // per-triangle 128x256 tiles
#define NTILES2 (NAB2 + 2 * NTRI2) // 4160

// ---------------- device scratch ----------------
__device__ float g_norm[NTOT];
__device__ float g_rowsum_aa[NHALF];
__device__ float g_rowsum_bb[NHALF];
__device__ float g_rowsum_ab[NHALF];
__device__ float g_colsum_ab[NHALF];
__device__ float g_alignneg;
__device__ float g_alignpart[1024];
__device__ float g_logsum;
__device__ unsigned int g_finctr;
__device__ __half g_h[(size_t)NTOT * DIMK];

__device__ __forceinline__ uint32_t s2u(const void* p) {
    uint32_t r;
    asm("{ .reg .u64 t; cvta.to.shared.u64 t, %1; cvt.u32.u64 %0, t; }"
        : "=r"(r) : "l"(p));
    return r;
}

__device__ __forceinline__ void mma_f16acc(uint32_t* d, const uint32_t* a, const uint32_t* b) {
    asm volatile(
        "mma.sync.aligned.m16n8k16.row.col.f16.f16.f16.f16 "
        "{%0,%1}, {%2,%3,%4,%5}, {%6,%7}, {%0,%1};"
        : "+r"(d[0]), "+r"(d[1])
        : "r"(a[0]), "r"(a[1]), "r"(a[2]), "r"(a[3]), "r"(b[0]), "r"(b[1]));
}

#define LDSM_X4(r0, r1, r2, r3, addr) \
    asm volatile("ldmatrix.sync.aligned.m8n8.x4.shared.b16 {%0,%1,%2,%3}, [%4];" \
                 : "=r"(r0), "=r"(r1), "=r"(r2), "=r"(r3) : "r"(addr))

__device__ __forceinline__ float frcp(float x) {
    float r;
    asm("rcp.approx.f32 %0, %1;" : "=f"(r) : "f"(x));
    return r;
}

// tile id -> (q, ti, tj2)
__device__ __forceinline__ void decode_tile(int id, int& q, int& ti, int& tj2) {
    if (id < NAB2) { q = 2; ti = id >> 5; tj2 = id & 31; return; }
    int t = id - NAB2;
    q = (t < NTRI2) ? 0 : 1;
    int u = q ? (t - NTRI2) : t;
    int s = (int)((65.f - sqrtf(4225.f - 4.f * (float)u)) * 0.5f);
    while (s > 0 && s * (65 - s) > u) s--;
    while ((s + 1) * (64 - s) <= u) s++;
    int rem = u - s * (65 - s);
    int cnt = 32 - s;
    int odd = (rem >= cnt) ? 1 : 0;
    ti = 2 * s + odd;
    tj2 = s + rem - (odd ? cnt : 0);
}

// ---------------- fused setup (single pass over F) ----------------
// blocks [0,1024): each warp handles row pair (r, r+NHALF): convert both to
// fp16, norms of ROUNDED values, alignment partial from exact f32.
// blocks [1024,1056): zero accumulators.
__global__ void setup_kernel(const float* __restrict__ F) {
    const int b = blockIdx.x;
    const int tid = threadIdx.x;
    const int wid = tid >> 5, lane = tid & 31;

    if (b < 1024) {
        __shared__ float sh[8];
        int gw = b * 8 + wid;
        float4 va = reinterpret_cast<const float4*>(F + (size_t)gw * DIMK)[lane];
        float4 vb = reinterpret_cast<const float4*>(F + (size_t)(gw + NHALF) * DIMK)[lane];
        __half2 a0 = __floats2half2_rn(va.x, va.y);
        __half2 a1 = __floats2half2_rn(va.z, va.w);
        __half2 b0 = __floats2half2_rn(vb.x, vb.y);
        __half2 b1 = __floats2half2_rn(vb.z, vb.w);
        __half2* da = reinterpret_cast<__half2*>(g_h + (size_t)gw * DIMK);
        __half2* db = reinterpret_cast<__half2*>(g_h + (size_t)(gw + NHALF) * DIMK);
        da[lane * 2 + 0] = a0; da[lane * 2 + 1] = a1;
        db[lane * 2 + 0] = b0; db[lane * 2 + 1] = b1;
        float2 fa0 = __half22float2(a0), fa1 = __half22float2(a1);
        float2 fb0 = __half22float2(b0), fb1 = __half22float2(b1);
        float na = fa0.x * fa0.x + fa0.y * fa0.y + fa1.x * fa1.x + fa1.y * fa1.y;
        float nb = fb0.x * fb0.x + fb0.y * fb0.y + fb1.x * fb1.x + fb1.y * fb1.y;
        float dx = va.x - vb.x, dy = va.y - vb.y, dz = va.z - vb.z, dw = va.w - vb.w;
        float dd = dx * dx + dy * dy + dz * dz + dw * dw;
        #pragma unroll
        for (int o = 16; o > 0; o >>= 1) {
            na += __shfl_xor_sync(0xffffffffu, na, o);
            nb += __shfl_xor_sync(0xffffffffu, nb, o);
            dd += __shfl_xor_sync(0xffffffffu, dd, o);
        }
        if (lane == 0) {
            g_norm[gw] = na;
            g_norm[gw + NHALF] = nb;
            sh[wid] = logf(1.f + dd);
        }
        __syncthreads();
        if (tid == 0) {
            float t = 0.f;
            #pragma unroll
            for (int i = 0; i < 8; i++) t += sh[i];
            g_alignpart[b] = t;
        }
    } else {
        int i = (b - 1024) * 256 + tid;
        g_rowsum_aa[i] = 0.f; g_rowsum_bb[i] = 0.f;
        g_rowsum_ab[i] = 0.f; g_colsum_ab[i] = 0.f;
        if (i == 0) { g_alignneg = 0.f; g_logsum = 0.f; g_finctr = 0u; }
    }
}

// ---------------- main tile kernel (128x256, f16 acc, sync-free epilogue) ----------------
__global__ void __launch_bounds__(256, 2) pair_mma_kernel() {
    extern __shared__ char sm[];
    __shared__ float sh_ni[128];
    __shared__ __half2 sh_nj2[128];

    int q, ti, tj2;
    decode_tile((int)blockIdx.x, q, ti, tj2);

    const int tid = threadIdx.x;
    const int wid = tid >> 5, lane = tid & 31;
    const int g = lane >> 2, t4 = lane & 3;
    const int rowOff = (wid >> 2) * 64;
    const int colOff = (wid & 3) * 64;

    const int iBase = ((q == 1) ? NHALF : 0) + ti * 128;
    const int jBase = ((q == 0) ? 0 : NHALF) + tj2 * 256;
    const uint32_t smbase = s2u(sm);

    // ---- async fill: four K quarters (24KB each), separate commit groups ----
    #pragma unroll
    for (int quarter = 0; quarter < 4; quarter++) {
        #pragma unroll
        for (int it = 0; it < 6; it++) {
            int c = tid + it * 256;            // 0..1535
            bool isA = c < 512;
            int c2 = isA ? c : (c - 512);
            int r = c2 >> 2;
            int kc = (c2 & 3) + quarter * 4;
            const __half* gp = g_h + (size_t)((isA ? iBase : jBase) + r) * DIMK + kc * 8;
            uint32_t dst = smbase + (isA ? 0u : 32768u) + r * 256 + ((kc ^ (r & 7)) << 4);
            asm volatile("cp.async.cg.shared.global [%0], [%1], 16;" :: "r"(dst), "l"(gp));
        }
        asm volatile("cp.async.commit_group;" ::: "memory");
    }

    if (tid < 128) {
        sh_ni[tid] = g_norm[iBase + tid];
    } else {
        int c = tid - 128;
        sh_nj2[c] = __floats2half2_rn(g_norm[jBase + 2 * c] + 1.f,
                                      g_norm[jBase + 2 * c + 1] + 1.f);
    }

    uint32_t acc[4][8][2];
    #pragma unroll
    for (int mt = 0; mt < 4; mt++)
        #pragma unroll
        for (int nt = 0; nt < 8; nt++) { acc[mt][nt][0] = 0u; acc[mt][nt][1] = 0u; }

    // ldmatrix addressing
    uint32_t aBase[4], bBase[4];
    int rsA[4], rsB[4];
    const int kbA = lane >> 4;
    const int kbB = (lane >> 3) & 1;
    #pragma unroll
    for (int mt = 0; mt < 4; mt++) {
        int row = rowOff + mt * 16 + (lane & 7) + ((lane >> 3) & 1) * 8;
        aBase[mt] = smbase + row * 256;
        rsA[mt] = row & 7;
    }
    #pragma unroll
    for (int bt = 0; bt < 4; bt++) {
        int nrow = colOff + bt * 16 + ((lane >> 4) * 8) + (lane & 7);
        bBase[bt] = smbase + 32768u + nrow * 256;
        rsB[bt] = nrow & 7;
    }

    // ---- mainloop: 4 quarters x 2 ksteps ----
    #pragma unroll
    for (int quarter = 0; quarter < 4; quarter++) {
        if (quarter == 0)      asm volatile("cp.async.wait_group 3;" ::: "memory");
        else if (quarter == 1) asm volatile("cp.async.wait_group 2;" ::: "memory");
        else if (quarter == 2) asm volatile("cp.async.wait_group 1;" ::: "memory");
        else                   asm volatile("cp.async.wait_group 0;" ::: "memory");
        __syncthreads();
        #pragma unroll
        for (int s = 0; s < 2; s++) {
            const int ks = quarter * 2 + s;
            uint32_t af[4][4], bf[8][2];
            #pragma unroll
            for (int mt = 0; mt < 4; mt++) {
                uint32_t addr = aBase[mt] + ((((2 * ks + kbA) ^ rsA[mt])) << 4);
                LDSM_X4(af[mt][0], af[mt][1], af[mt][2], af[mt][3], addr);
            }
            #pragma unroll
            for (int bt = 0; bt < 4; bt++) {
                uint32_t addr = bBase[bt] + ((((2 * ks + kbB) ^ rsB[bt])) << 4);
                LDSM_X4(bf[bt * 2][0], bf[bt * 2][1], bf[bt * 2 + 1][0], bf[bt * 2 + 1][1], addr);
            }
            #pragma unroll
            for (int mt = 0; mt < 4; mt++)
                #pragma unroll
                for (int nt = 0; nt < 8; nt++)
                    mma_f16acc(acc[mt][nt], af[mt], bf[nt]);
        }
    }

    // ---- epilogue (sync-free: shuffles + direct atomics) ----
    const bool crossing = (q < 2) && (tj2 == (ti >> 1));

    __half2 rn2[8], cn2[8];
    #pragma unroll
    for (int mt = 0; mt < 4; mt++) {
        rn2[2 * mt + 0] = __float2half2_rn(sh_ni[rowOff + mt * 16 + g]);
        rn2[2 * mt + 1] = __float2half2_rn(sh_ni[rowOff + mt * 16 + g + 8]);
    }
    #pragma unroll
    for (int nt = 0; nt < 8; nt++)
        cn2[nt] = sh_nj2[colOff / 2 + nt * 4 + t4];

    __half2 rowH2[8], colH2[8];
    float rowsum[8];
    #pragma unroll
    for (int i = 0; i < 8; i++) {
        rowH2[i] = __float2half2_rn(0.f);
        colH2[i] = __float2half2_rn(0.f);
        rowsum[i] = 0.f;
    }

    if (!crossing) {
        const __half2 m2 = __float2half2_rn(-2.f);
        #pragma unroll
        for (int mt = 0; mt < 4; mt++)
            #pragma unroll
            for (int nt = 0; nt < 8; nt++)
                #pragma unroll
                for (int h = 0; h < 2; h++) {
                    __half2 a2 = *reinterpret_cast<__half2*>(&acc[mt][nt][h]);
                    __half2 sim = h2rcp(__hfma2(a2, m2, __hadd2(rn2[2 * mt + h], cn2[nt])));
                    rowH2[2 * mt + h] = __hadd2(rowH2[2 * mt + h], sim);
                    colH2[nt] = __hadd2(colH2[nt], sim);
                }
        #pragma unroll
        for (int i = 0; i < 8; i++) {
            __half2 v = rowH2[i];
            rowsum[i] = __low2float(v) + __high2float(v);
        }
    } else {
        // exact f32 path with col>row masking (64 of 4160 tiles)
        #pragma unroll
        for (int mt = 0; mt < 4; mt++)
            #pragma unroll
            for (int nt = 0; nt < 8; nt++)
                #pragma unroll
                for (int h = 0; h < 2; h++) {
                    float2 a2 = __half22float2(*reinterpret_cast<__half2*>(&acc[mt][nt][h]));
                    float2 cnf = __half22float2(cn2[nt]);
                    float rni = sh_ni[rowOff + mt * 16 + g + h * 8];
                    int grow = ti * 128 + rowOff + mt * 16 + g + h * 8;
                    int gcol = tj2 * 256 + colOff + nt * 8 + 2 * t4;
                    float s0 = frcp(fmaf(-2.f, a2.x, rni + cnf.x));
                    float s1 = frcp(fmaf(-2.f, a2.y, rni + cnf.y));
                    if (gcol     <= grow) s0 = 0.f;
                    if (gcol + 1 <= grow) s1 = 0.f;
                    rowsum[2 * mt + h] += s0 + s1;
                    float2 cc = __half22float2(colH2[nt]);
                    colH2[nt] = __floats2half2_rn(cc.x + s0, cc.y + s1);
                }
    }

    float* rdst = (q == 0) ? g_rowsum_aa : ((q == 1) ? g_rowsum_bb : g_rowsum_ab);
    float* cdst = (q == 2) ? g_colsum_ab : ((q == 0) ? g_rowsum_aa : g_rowsum_bb);

    // rows: reduce over t4 lanes, then direct atomics from t4==0
    #pragma unroll
    for (int i = 0; i < 8; i++) {
        rowsum[i] += __shfl_xor_sync(0xffffffffu, rowsum[i], 1);
        rowsum[i] += __shfl_xor_sync(0xffffffffu, rowsum[i], 2);
    }
    if (t4 == 0) {
        #pragma unroll
        for (int mt = 0; mt < 4; mt++) {
            atomicAdd(&rdst[ti * 128 + rowOff + mt * 16 + g],     rowsum[2 * mt + 0]);
            atomicAdd(&rdst[ti * 128 + rowOff + mt * 16 + g + 8], rowsum[2 * mt + 1]);
        }
    }
    // cols: half2 reduce over g lanes, direct atomics from g==0
    #pragma unroll
    for (int nt = 0; nt < 8; nt++) {
        colH2[nt] = __hadd2(colH2[nt], __shfl_xor_sync(0xffffffffu, colH2[nt], 4));
        colH2[nt] = __hadd2(colH2[nt], __shfl_xor_sync(0xffffffffu, colH2[nt], 8));
        colH2[nt] = __hadd2(colH2[nt], __shfl_xor_sync(0xffffffffu, colH2[nt], 16));
    }
    if (g == 0) {
        #pragma unroll
        for (int nt = 0; nt < 8; nt++) {
            int c = tj2 * 256 + colOff + nt * 8 + 2 * t4;
            atomicAdd(&cdst[c],     __low2float(colH2[nt]));
            atomicAdd(&cdst[c + 1], __high2float(colH2[nt]));
        }
    }
}

// ---------------- fused finalize (last-block-done) ----------------
__global__ void finalize_kernel(float* __restrict__ out) {
    __shared__ bool isLast;
    int idx = blockIdx.x * 256 + threadIdx.x;
    float s = 0.f;
    for (int j = idx; j < NHALF; j += 4096) {
        s += logf(g_colsum_ab[j] + g_rowsum_bb[j]);
        s += logf(g_rowsum_aa[j] + g_rowsum_ab[j]);
    }
    #pragma unroll
    for (int o = 16; o > 0; o >>= 1) s += __shfl_xor_sync(0xffffffffu, s, o);
    if ((threadIdx.x & 31) == 0) atomicAdd(&g_logsum, s);

    if (blockIdx.x == 0) {
        float a = 0.f;
        for (int j = threadIdx.x; j < 1024; j += 256) a += g_alignpart[j];
        #pragma unroll
        for (int o = 16; o > 0; o >>= 1) a += __shfl_xor_sync(0xffffffffu, a, o);
        if ((threadIdx.x & 31) == 0) atomicAdd(&g_alignneg, a);
    }

    __threadfence();
    __syncthreads();
    if (threadIdx.x == 0) isLast = (atomicAdd(&g_finctr, 1u) == 15u);
    __syncthreads();
    if (isLast && threadIdx.x == 0)
        out[0] = g_alignneg / (float)NHALF + 0.5f * g_logsum / (float)NHALF;
}

// ---------------- launch ----------------
extern "C" void kernel_launch(void* const* d_in, const int* in_sizes, int n_in,
                              void* d_out, int out_size) {
    const float* F = (const float*)d_in[0];
    float* out = (float*)d_out;

    const int SMEM_BYTES = 98304;
    cudaFuncSetAttribute(pair_mma_kernel,
                         cudaFuncAttributeMaxDynamicSharedMemorySize, SMEM_BYTES);

    setup_kernel<<<1056, 256>>>(F);
    pair_mma_kernel<<<NTILES2, 256, SMEM_BYTES>>>();
    finalize_kernel<<<16, 256>>>(out);
}

// round 11
// speedup vs baseline: 1.5547x; 1.5547x over previous
#include <cuda_runtime.h>
#include <cuda_fp16.h>
#include <math.h>
#include <stdint.h>

#define NHALF 8192
#define NTOT  16384
#define DIMK  128
#define NAB2  2048                 // 64 x 32 ab tiles (128x256)
#define NTRI2 1056                 // per-triangle 128x256 tiles
#define NTILES2 (NAB2 + 2 * NTRI2) // 4160

// ---------------- device scratch ----------------
__device__ float g_norm[NTOT];
__device__ float g_rowsum_aa[NHALF];
__device__ float g_rowsum_bb[NHALF];
__device__ float g_rowsum_ab[NHALF];
__device__ float g_colsum_ab[NHALF];
__device__ float g_alignneg;
__device__ float g_alignpart[1024];
__device__ float g_logsum;
__device__ unsigned int g_finctr;
__device__ __half g_h[(size_t)NTOT * DIMK];

__device__ __forceinline__ uint32_t s2u(const void* p) {
    uint32_t r;
    asm("{ .reg .u64 t; cvta.to.shared.u64 t, %1; cvt.u32.u64 %0, t; }"
        : "=r"(r) : "l"(p));
    return r;
}

// fp16-accumulate MMA: D,C are 2 b32 regs (half2 pairs).
__device__ __forceinline__ void mma_f16acc(uint32_t* d, const uint32_t* a, const uint32_t* b) {
    asm volatile(
        "mma.sync.aligned.m16n8k16.row.col.f16.f16.f16.f16 "
        "{%0,%1}, {%2,%3,%4,%5}, {%6,%7}, {%0,%1};"
        : "+r"(d[0]), "+r"(d[1])
        : "r"(a[0]), "r"(a[1]), "r"(a[2]), "r"(a[3]), "r"(b[0]), "r"(b[1]));
}

#define LDSM_X4(r0, r1, r2, r3, addr) \
    asm volatile("ldmatrix.sync.aligned.m8n8.x4.shared.b16 {%0,%1,%2,%3}, [%4];" \
                 : "=r"(r0), "=r"(r1), "=r"(r2), "=r"(r3) : "r"(addr))

__device__ __forceinline__ float frcp(float x) {
    float r;
    asm("rcp.approx.f32 %0, %1;" : "=f"(r) : "f"(x));
    return r;
}

// tile id -> (q, ti, tj2). id<NAB2: ab. Then aa, bb (rows ti:128, cols tj2:256,
// keep tiles with tj2 >= ti>>1; tj2 == ti>>1 crosses the diagonal).
__device__ __forceinline__ void decode_tile(int id, int& q, int& ti, int& tj2) {
    if (id < NAB2) { q = 2; ti = id >> 5; tj2 = id & 31; return; }
    int t = id - NAB2;
    q = (t < NTRI2) ? 0 : 1;
    int u = q ? (t - NTRI2) : t;
    int s = (int)((65.f - sqrtf(4225.f - 4.f * (float)u)) * 0.5f);
    while (s > 0 && s * (65 - s) > u) s--;
    while ((s + 1) * (64 - s) <= u) s++;
    int rem = u - s * (65 - s);
    int cnt = 32 - s;
    int odd = (rem >= cnt) ? 1 : 0;
    ti = 2 * s + odd;
    tj2 = s + rem - (odd ? cnt : 0);
}

// ---------------- fused setup kernel (R8 variant, measured 7.0us) ----------------
// blocks [0,2048): fp32->fp16 convert + norms (8 rows/block)
// blocks [2048,3072): alignment partials -> g_alignpart (8 rows/block)
// blocks [3072,3104): zero accumulators
__global__ void setup_kernel(const float* __restrict__ F) {
    const int b = blockIdx.x;
    const int tid = threadIdx.x;
    const int wid = tid >> 5, lane = tid & 31;

    if (b < 2048) {
        int gw = b * 8 + wid;
        float4 v = reinterpret_cast<const float4*>(F + (size_t)gw * DIMK)[lane];
        __half2 h0 = __floats2half2_rn(v.x, v.y);
        __half2 h1 = __floats2half2_rn(v.z, v.w);
        __half2* dst = reinterpret_cast<__half2*>(g_h + (size_t)gw * DIMK);
        dst[lane * 2 + 0] = h0;
        dst[lane * 2 + 1] = h1;
        float2 c0 = __half22float2(h0), c1 = __half22float2(h1);
        float s = c0.x * c0.x + c0.y * c0.y + c1.x * c1.x + c1.y * c1.y;
        #pragma unroll
        for (int o = 16; o > 0; o >>= 1) s += __shfl_xor_sync(0xffffffffu, s, o);
        if (lane == 0) g_norm[gw] = s;
    } else if (b < 3072) {
        __shared__ float sh[8];
        int gw = (b - 2048) * 8 + wid;
        float4 a = reinterpret_cast<const float4*>(F + (size_t)gw * DIMK)[lane];
        float4 bb = reinterpret_cast<const float4*>(F + (size_t)(gw + NHALF) * DIMK)[lane];
        float dx = a.x - bb.x, dy = a.y - bb.y, dz = a.z - bb.z, dw = a.w - bb.w;
        float s = dx * dx + dy * dy + dz * dz + dw * dw;
        #pragma unroll
        for (int o = 16; o > 0; o >>= 1) s += __shfl_xor_sync(0xffffffffu, s, o);
        if (lane == 0) sh[wid] = logf(1.f + s);
        __syncthreads();
        if (tid == 0) {
            float t = 0.f;
            #pragma unroll
            for (int i = 0; i < 8; i++) t += sh[i];
            g_alignpart[b - 2048] = t;
        }
    } else {
        int i = (b - 3072) * 256 + tid;
        if (i < NHALF) {
            g_rowsum_aa[i] = 0.f; g_rowsum_bb[i] = 0.f;
            g_rowsum_ab[i] = 0.f; g_colsum_ab[i] = 0.f;
        }
        if (i == 0) { g_alignneg = 0.f; g_logsum = 0.f; g_finctr = 0u; }
    }
}

// ---------------- main tile kernel (R7 verbatim: 128x256 tile, f16 acc) ----------------
// Smem: A 128x256B (32KB) @0, B 256x256B (64KB) @32768.
// chunk kc of row r at base + r*256 + ((kc^(r&7))<<4).
__global__ void __launch_bounds__(256, 2) pair_mma_kernel() {
    extern __shared__ char sm[];
    __shared__ float sh_ni[128];
    __shared__ __half2 sh_nj2[128];       // (norm+1) pairs for 256 cols
    __shared__ float rowAcc[128][4];
    __shared__ float colAcc[256][2];

    int q, ti, tj2;
    decode_tile((int)blockIdx.x, q, ti, tj2);

    const int tid = threadIdx.x;
    const int wid = tid >> 5, lane = tid & 31;
    const int g = lane >> 2, t4 = lane & 3;
    const int rowOff = (wid >> 2) * 64;       // 0 / 64
    const int colOff = (wid & 3) * 64;        // 0..192

    const int iBase = ((q == 1) ? NHALF : 0) + ti * 128;
    const int jBase = ((q == 0) ? 0 : NHALF) + tj2 * 256;
    const uint32_t smbase = s2u(sm);

    // ---- async fill: two K halves, 12 chunks/thread each ----
    #pragma unroll
    for (int half = 0; half < 2; half++) {
        #pragma unroll
        for (int it = 0; it < 6; it++) {
            int c = tid + it * 256;           // 0..1535 -> A:0..1023, B first part
            bool isA = c < 1024;
            int r = isA ? (c >> 3) : ((c - 1024) >> 3);
            int kc = (c & 7) + half * 8;
            const __half* gp = g_h + (size_t)((isA ? iBase : jBase) + r) * DIMK + kc * 8;
            uint32_t dst = smbase + (isA ? 0u : 32768u) + r * 256 + ((kc ^ (r & 7)) << 4);
            asm volatile("cp.async.cg.shared.global [%0], [%1], 16;" :: "r"(dst), "l"(gp));
        }
        #pragma unroll
        for (int it = 6; it < 12; it++) {     // B rows 64..255
            int c = tid + it * 256;
            int r = (c - 1024) >> 3;
            int kc = (c & 7) + half * 8;
            const __half* gp = g_h + (size_t)(jBase + r) * DIMK + kc * 8;
            uint32_t dst = smbase + 32768u + r * 256 + ((kc ^ (r & 7)) << 4);
            asm volatile("cp.async.cg.shared.global [%0], [%1], 16;" :: "r"(dst), "l"(gp));
        }
        asm volatile("cp.async.commit_group;" ::: "memory");
    }

    if (tid < 128) {
        sh_ni[tid] = g_norm[iBase + tid];
    } else {
        int c = tid - 128;
        sh_nj2[c] = __floats2half2_rn(g_norm[jBase + 2 * c] + 1.f,
                                      g_norm[jBase + 2 * c + 1] + 1.f);
    }

    uint32_t acc[4][8][2];
    #pragma unroll
    for (int mt = 0; mt < 4; mt++)
        #pragma unroll
        for (int nt = 0; nt < 8; nt++) { acc[mt][nt][0] = 0u; acc[mt][nt][1] = 0u; }

    // ldmatrix per-lane addressing
    uint32_t aBase[4], bBase[4];
    int rsA[4], rsB[4];
    const int kbA = lane >> 4;
    const int kbB = (lane >> 3) & 1;
    #pragma unroll
    for (int mt = 0; mt < 4; mt++) {
        int row = rowOff + mt * 16 + (lane & 7) + ((lane >> 3) & 1) * 8;
        aBase[mt] = smbase + row * 256;
        rsA[mt] = row & 7;
    }
    #pragma unroll
    for (int bt = 0; bt < 4; bt++) {
        int nrow = colOff + bt * 16 + ((lane >> 4) * 8) + (lane & 7);
        bBase[bt] = smbase + 32768u + nrow * 256;
        rsB[bt] = nrow & 7;
    }

    // ---- mainloop ----
    #pragma unroll
    for (int half = 0; half < 2; half++) {
        if (half == 0) asm volatile("cp.async.wait_group 1;" ::: "memory");
        else           asm volatile("cp.async.wait_group 0;" ::: "memory");
        __syncthreads();
        #pragma unroll
        for (int ks2 = 0; ks2 < 4; ks2++) {
            const int ks = half * 4 + ks2;
            uint32_t af[4][4], bf[8][2];
            #pragma unroll
            for (int mt = 0; mt < 4; mt++) {
                uint32_t addr = aBase[mt] + ((((2 * ks + kbA) ^ rsA[mt])) << 4);
                LDSM_X4(af[mt][0], af[mt][1], af[mt][2], af[mt][3], addr);
            }
            #pragma unroll
            for (int bt = 0; bt < 4; bt++) {
                uint32_t addr = bBase[bt] + ((((2 * ks + kbB) ^ rsB[bt])) << 4);
                LDSM_X4(bf[bt * 2][0], bf[bt * 2][1], bf[bt * 2 + 1][0], bf[bt * 2 + 1][1], addr);
            }
            #pragma unroll
            for (int mt = 0; mt < 4; mt++)
                #pragma unroll
                for (int nt = 0; nt < 8; nt++)
                    mma_f16acc(acc[mt][nt], af[mt], bf[nt]);
        }
    }

    // ---- epilogue ----
    const bool crossing = (q < 2) && (tj2 == (ti >> 1));

    __half2 rowH2[8], colH2[8];
    float rowsum[8];
    #pragma unroll
    for (int i = 0; i < 8; i++) {
        rowH2[i] = __float2half2_rn(0.f);
        colH2[i] = __float2half2_rn(0.f);
        rowsum[i] = 0.f;
    }

    __half2 rn2[8];
    __half2 cn2[8];
    #pragma unroll
    for (int mt = 0; mt < 4; mt++) {
        rn2[2 * mt + 0] = __float2half2_rn(sh_ni[rowOff + mt * 16 + g]);
        rn2[2 * mt + 1] = __float2half2_rn(sh_ni[rowOff + mt * 16 + g + 8]);
    }
    #pragma unroll
    for (int nt = 0; nt < 8; nt++)
        cn2[nt] = sh_nj2[(colOff + nt * 8) / 2 + t4];

    if (!crossing) {
        const __half2 m2 = __float2half2_rn(-2.f);
        #pragma unroll
        for (int mt = 0; mt < 4; mt++)
            #pragma unroll
            for (int nt = 0; nt < 8; nt++)
                #pragma unroll
                for (int h = 0; h < 2; h++) {
                    __half2 a2 = *reinterpret_cast<__half2*>(&acc[mt][nt][h]);
                    __half2 arg = __hfma2(a2, m2, __hadd2(rn2[2 * mt + h], cn2[nt]));
                    __half2 sim = h2rcp(arg);
                    rowH2[2 * mt + h] = __hadd2(rowH2[2 * mt + h], sim);
                    colH2[nt] = __hadd2(colH2[nt], sim);
                }
        // fold half2 row partials into f32
        #pragma unroll
        for (int i = 0; i < 8; i++) {
            __half2 v = rowH2[i];
            rowsum[i] = __low2float(v) + __high2float(v);
        }
    } else {
        // exact f32 path with col>row masking (diag-crossing tiles only)
        #pragma unroll
        for (int mt = 0; mt < 4; mt++)
            #pragma unroll
            for (int nt = 0; nt < 8; nt++)
                #pragma unroll
                for (int h = 0; h < 2; h++) {
                    float2 a2 = __half22float2(*reinterpret_cast<__half2*>(&acc[mt][nt][h]));
                    float2 cnf = __half22float2(cn2[nt]);
                    float rni = sh_ni[rowOff + mt * 16 + g + h * 8];
                    int grow = ti * 128 + rowOff + mt * 16 + g + h * 8;
                    int gcol = tj2 * 256 + colOff + nt * 8 + 2 * t4;
                    float s0 = frcp(fmaf(-2.f, a2.x, rni + cnf.x));
                    float s1 = frcp(fmaf(-2.f, a2.y, rni + cnf.y));
                    if (gcol     <= grow) s0 = 0.f;
                    if (gcol + 1 <= grow) s1 = 0.f;
                    rowsum[2 * mt + h] += s0 + s1;
                    float2 cc = __half22float2(colH2[nt]);
                    colH2[nt] = __floats2half2_rn(cc.x + s0, cc.y + s1);
                }
    }

    // ---- reductions ----
    // rows: reduce over t4 (xor 1,2)
    #pragma unroll
    for (int i = 0; i < 8; i++) {
        rowsum[i] += __shfl_xor_sync(0xffffffffu, rowsum[i], 1);
        rowsum[i] += __shfl_xor_sync(0xffffffffu, rowsum[i], 2);
    }
    if (t4 == 0) {
        #pragma unroll
        for (int mt = 0; mt < 4; mt++) {
            rowAcc[rowOff + mt * 16 + g][wid & 3]     = rowsum[2 * mt + 0];
            rowAcc[rowOff + mt * 16 + g + 8][wid & 3] = rowsum[2 * mt + 1];
        }
    }
    // cols: reduce half2 over g (xor 4,8,16)
    #pragma unroll
    for (int i = 0; i < 8; i++) {
        colH2[i] = __hadd2(colH2[i], __shfl_xor_sync(0xffffffffu, colH2[i], 4));
        colH2[i] = __hadd2(colH2[i], __shfl_xor_sync(0xffffffffu, colH2[i], 8));
        colH2[i] = __hadd2(colH2[i], __shfl_xor_sync(0xffffffffu, colH2[i], 16));
    }
    if (g == 0) {
        #pragma unroll
        for (int nt = 0; nt < 8; nt++) {
            colAcc[colOff + nt * 8 + 2 * t4][wid >> 2]     = __low2float(colH2[nt]);
            colAcc[colOff + nt * 8 + 2 * t4 + 1][wid >> 2] = __high2float(colH2[nt]);
        }
    }
    __syncthreads();

    if (tid < 128) {
        float s = rowAcc[tid][0] + rowAcc[tid][1] + rowAcc[tid][2] + rowAcc[tid][3];
        float* dst = (q == 0) ? g_rowsum_aa : ((q == 1) ? g_rowsum_bb : g_rowsum_ab);
        atomicAdd(&dst[ti * 128 + tid], s);
    }
    {
        int c = tid;          // all 256 threads: one column each
        float s = colAcc[c][0] + colAcc[c][1];
        if (q == 2) {
            atomicAdd(&g_colsum_ab[tj2 * 256 + c], s);
        } else {
            // mirror strict-upper contributions into the column row
            atomicAdd((q == 0) ? &g_rowsum_aa[tj2 * 256 + c]
                               : &g_rowsum_bb[tj2 * 256 + c], s);
        }
    }
}

// ---------------- fused finalize (last-block-done) ----------------
__global__ void finalize_kernel(float* __restrict__ out) {
    __shared__ bool isLast;
    int idx = blockIdx.x * 256 + threadIdx.x;
    float s = 0.f;
    for (int j = idx; j < NHALF; j += 4096) {
        s += logf(g_colsum_ab[j] + g_rowsum_bb[j]);
        s += logf(g_rowsum_aa[j] + g_rowsum_ab[j]);
    }
    #pragma unroll
    for (int o = 16; o > 0; o >>= 1) s += __shfl_xor_sync(0xffffffffu, s, o);
    if ((threadIdx.x & 31) == 0) atomicAdd(&g_logsum, s);

    if (blockIdx.x == 0) {
        float a = 0.f;
        for (int j = threadIdx.x; j < 1024; j += 256) a += g_alignpart[j];
        #pragma unroll
        for (int o = 16; o > 0; o >>= 1) a += __shfl_xor_sync(0xffffffffu, a, o);
        if ((threadIdx.x & 31) == 0) atomicAdd(&g_alignneg, a);
    }

    __threadfence();
    __syncthreads();
    if (threadIdx.x == 0) isLast = (atomicAdd(&g_finctr, 1u) == 15u);
    __syncthreads();
    if (isLast && threadIdx.x == 0)
        out[0] = g_alignneg / (float)NHALF + 0.5f * g_logsum / (float)NHALF;
}

// ---------------- launch ----------------
extern "C" void kernel_launch(void* const* d_in, const int* in_sizes, int n_in,
                              void* d_out, int out_size) {
    const float* F = (const float*)d_in[0];
    float* out = (float*)d_out;

    const int SMEM_BYTES = 98304;   // A 32KB + B 64KB
    cudaFuncSetAttribute(pair_mma_kernel,
                         cudaFuncAttributeMaxDynamicSharedMemorySize, SMEM_BYTES);

    setup_kernel<<<3104, 256>>>(F);
    pair_mma_kernel<<<NTILES2, 256, SMEM_BYTES>>>();
    finalize_kernel<<<16, 256>>>(out);
}